// round 2
// baseline (speedup 1.0000x reference)
#include <cuda_runtime.h>
#include <math.h>

#define DIM    256
#define HEADS  8
#define HD     32
#define N1V    256
#define N2V    256
#define BTOT   256
#define NWIN   128
#define TBL    1575

// ---------------- scratch (device globals; no allocation) ----------------
__device__ float d_qh [BTOT * N1V * DIM];        // (B*N1, C)  scaled Q proj
__device__ float d_kvh[BTOT * N2V * 2 * DIM];    // (B*N2, 2C) K|V proj
__device__ float d_x  [BTOT * N1V * DIM];        // (B*N1, C)  attn output

// ---------------- generic NT SGEMM: C = alpha * (A @ B^T + bias) ----------
// A: [M,K] row-major, B: [N,K] row-major, bias: [N]
// block tile 128x128, k-tile 16, 256 threads, 8x8 per thread
__global__ void __launch_bounds__(256) gemm_nt(
    const float* __restrict__ A, const float* __restrict__ B,
    const float* __restrict__ bias, float* __restrict__ C,
    int M, int N, int K, float alpha)
{
    __shared__ float As[16][132];
    __shared__ float Bs[16][132];
    const int m0  = blockIdx.y * 128;
    const int n0  = blockIdx.x * 128;
    const int tid = threadIdx.x;
    const int tr  = tid >> 4;     // 0..15
    const int tc  = tid & 15;     // 0..15

    float acc[8][8];
#pragma unroll
    for (int i = 0; i < 8; i++)
#pragma unroll
        for (int j = 0; j < 8; j++) acc[i][j] = 0.f;

    for (int k0 = 0; k0 < K; k0 += 16) {
#pragma unroll
        for (int i = 0; i < 2; i++) {
            int li = tid + i * 256;          // 0..511 float4 slots
            int r  = li >> 2;                // 0..127
            int cq = (li & 3) << 2;          // 0,4,8,12
            float4 va = *(const float4*)(A + (size_t)(m0 + r) * K + k0 + cq);
            As[cq + 0][r] = va.x; As[cq + 1][r] = va.y;
            As[cq + 2][r] = va.z; As[cq + 3][r] = va.w;
            float4 vb = *(const float4*)(B + (size_t)(n0 + r) * K + k0 + cq);
            Bs[cq + 0][r] = vb.x; Bs[cq + 1][r] = vb.y;
            Bs[cq + 2][r] = vb.z; Bs[cq + 3][r] = vb.w;
        }
        __syncthreads();
#pragma unroll
        for (int kk = 0; kk < 16; kk++) {
            float a[8], b[8];
#pragma unroll
            for (int i = 0; i < 8; i++) a[i] = As[kk][tr * 8 + i];
#pragma unroll
            for (int j = 0; j < 8; j++) b[j] = Bs[kk][tc * 8 + j];
#pragma unroll
            for (int i = 0; i < 8; i++)
#pragma unroll
                for (int j = 0; j < 8; j++)
                    acc[i][j] = fmaf(a[i], b[j], acc[i][j]);
        }
        __syncthreads();
    }

#pragma unroll
    for (int i = 0; i < 8; i++) {
        int r = m0 + tr * 8 + i;
#pragma unroll
        for (int j = 0; j < 8; j++) {
            int c = n0 + tc * 8 + j;
            C[(size_t)r * N + c] = alpha * (acc[i][j] + bias[c]);
        }
    }
}

// ---------------- attention kernel ----------------
// grid: (4 q-tiles of 64, HEADS, BTOT), 256 threads
// thread (tx = tid&63 -> query in tile, ty = tid>>6 -> 64-key chunk)
struct __align__(16) AttnSmem {
    union U {
        float K[256][32];                             // K tile, then V tile (broadcast reads)
        struct { float Ms[64][65]; unsigned short Ri[64][66]; } mb;  // mask + rel chunk
    } u;                                              // 32768 B
    float Qs[64][33];                                 // Q tile, reused as O accumulator
    float btab[TBL];                                  // bias_table column h
    float red[64][4];
    float linv[64];
};

__global__ void __launch_bounds__(256) attn_kernel(
    const float* __restrict__ qh, const float* __restrict__ kvh,
    const float* __restrict__ mask, const float* __restrict__ btab_g,
    const int* __restrict__ rel, float* __restrict__ xout)
{
    __shared__ AttnSmem sm;
    const int tid = threadIdx.x;
    const int tx  = tid & 63;
    const int ty  = tid >> 6;
    const int q0  = blockIdx.x * 64;
    const int h   = blockIdx.y;
    const int b   = blockIdx.z;
    const int w   = b & (NWIN - 1);

    // bias table column for this head (1575 floats)
    for (int i = tid; i < TBL; i += 256)
        sm.btab[i] = btab_g[i * HEADS + h];

    // load Q tile (64 x 32) and K tile (256 x 32)
    {
        const float* qbase = qh + ((size_t)(b * N1V + q0)) * DIM + h * HD;
#pragma unroll
        for (int i = 0; i < 2; i++) {
            int li = tid + i * 256;          // 0..511
            int r  = li >> 3;                // 0..63
            int cq = (li & 7) << 2;          // 0..28
            float4 v = *(const float4*)(qbase + (size_t)r * DIM + cq);
            sm.Qs[r][cq] = v.x; sm.Qs[r][cq + 1] = v.y;
            sm.Qs[r][cq + 2] = v.z; sm.Qs[r][cq + 3] = v.w;
        }
        const float* kbase = kvh + ((size_t)b * N2V) * (2 * DIM) + h * HD;
#pragma unroll
        for (int i = 0; i < 8; i++) {
            int li = tid + i * 256;          // 0..2047
            int r  = li >> 3;                // 0..255
            int cq = (li & 7) << 2;
            float4 v = *(const float4*)(kbase + (size_t)r * (2 * DIM) + cq);
            sm.u.K[r][cq] = v.x; sm.u.K[r][cq + 1] = v.y;
            sm.u.K[r][cq + 2] = v.z; sm.u.K[r][cq + 3] = v.w;
        }
    }
    __syncthreads();

    // hoist Q row into registers, compute raw S chunk (64 keys per thread)
    float qreg[32];
#pragma unroll
    for (int c = 0; c < 32; c++) qreg[c] = sm.Qs[tx][c];

    float s[64];
#pragma unroll
    for (int j = 0; j < 64; j++) {
        const float* krow = sm.u.K[ty * 64 + j];
        float acc = 0.f;
#pragma unroll
        for (int c = 0; c < 32; c++) acc = fmaf(qreg[c], krow[c], acc);
        s[j] = acc;
    }
    __syncthreads();   // done with K region and Qs

    // add mask + relative-position bias, staged through smem (coalesced)
    for (int ch = 0; ch < 4; ch++) {
#pragma unroll
        for (int i = 0; i < 4; i++) {
            int li = tid + i * 256;          // 0..1023 float4 slots (64x64)
            int r  = li >> 4;                // 0..63
            int cq = (li & 15) << 2;         // 0..60
            float4 mv = *(const float4*)(mask + ((size_t)(w * N1V + q0 + r)) * N2V + ch * 64 + cq);
            sm.u.mb.Ms[r][cq] = mv.x; sm.u.mb.Ms[r][cq + 1] = mv.y;
            sm.u.mb.Ms[r][cq + 2] = mv.z; sm.u.mb.Ms[r][cq + 3] = mv.w;
            int4 rv = *(const int4*)(rel + (size_t)(q0 + r) * N2V + ch * 64 + cq);
            sm.u.mb.Ri[r][cq]     = (unsigned short)rv.x;
            sm.u.mb.Ri[r][cq + 1] = (unsigned short)rv.y;
            sm.u.mb.Ri[r][cq + 2] = (unsigned short)rv.z;
            sm.u.mb.Ri[r][cq + 3] = (unsigned short)rv.w;
        }
        __syncthreads();
        if (ty == ch) {
#pragma unroll
            for (int j = 0; j < 64; j++)
                s[j] += sm.u.mb.Ms[tx][j] + sm.btab[sm.u.mb.Ri[tx][j]];
        }
        __syncthreads();
    }

    // softmax over 256 keys (4 chunks of 64 across ty)
    float m = -1e30f;
#pragma unroll
    for (int j = 0; j < 64; j++) m = fmaxf(m, s[j]);
    sm.red[tx][ty] = m;
    __syncthreads();
    m = fmaxf(fmaxf(sm.red[tx][0], sm.red[tx][1]),
              fmaxf(sm.red[tx][2], sm.red[tx][3]));
    __syncthreads();
    float lsum = 0.f;
#pragma unroll
    for (int j = 0; j < 64; j++) {
        float e = __expf(s[j] - m);
        s[j] = e;
        lsum += e;
    }
    sm.red[tx][ty] = lsum;
    __syncthreads();
    float l = sm.red[tx][0] + sm.red[tx][1] + sm.red[tx][2] + sm.red[tx][3];
    if (ty == 0) sm.linv[tx] = 1.0f / l;

    // load V into the K region (previous users are past the last sync)
    {
        const float* vbase = kvh + ((size_t)b * N2V) * (2 * DIM) + DIM + h * HD;
#pragma unroll
        for (int i = 0; i < 8; i++) {
            int li = tid + i * 256;
            int r  = li >> 3;
            int cq = (li & 7) << 2;
            float4 v = *(const float4*)(vbase + (size_t)r * (2 * DIM) + cq);
            sm.u.K[r][cq] = v.x; sm.u.K[r][cq + 1] = v.y;
            sm.u.K[r][cq + 2] = v.z; sm.u.K[r][cq + 3] = v.w;
        }
    }
    __syncthreads();

    // O partial: each thread accumulates its 64-key chunk over all 32 dims
    float o[32];
#pragma unroll
    for (int d = 0; d < 32; d++) o[d] = 0.f;
#pragma unroll
    for (int j = 0; j < 64; j++) {
        float p = s[j];
        const float* vrow = sm.u.K[ty * 64 + j];
#pragma unroll
        for (int d = 0; d < 32; d++) o[d] = fmaf(p, vrow[d], o[d]);
    }

    // reduce 4 partial O vectors per query through Qs (reused as accumulator)
    for (int st = 0; st < 4; st++) {
        if (ty == st) {
            if (st == 0) {
#pragma unroll
                for (int d = 0; d < 32; d++) sm.Qs[tx][d] = o[d];
            } else {
#pragma unroll
                for (int d = 0; d < 32; d++) sm.Qs[tx][d] += o[d];
            }
        }
        __syncthreads();
    }

    // write x[b, q, h*32+d] = O / l   (coalesced)
#pragma unroll
    for (int i = 0; i < 8; i++) {
        int lin = tid + i * 256;             // 0..2047
        int q   = lin >> 5;
        int d   = lin & 31;
        xout[((size_t)(b * N1V + q0 + q)) * DIM + h * HD + d] =
            sm.Qs[q][d] * sm.linv[q];
    }
}

// ---------------- launch ----------------
extern "C" void kernel_launch(void* const* d_in, const int* in_sizes, int n_in,
                              void* d_out, int out_size)
{
    const float* q    = (const float*)d_in[0];
    const float* kv   = (const float*)d_in[1];
    const float* mask = (const float*)d_in[2];
    const float* Wq   = (const float*)d_in[3];
    const float* bq   = (const float*)d_in[4];
    const float* Wkv  = (const float*)d_in[5];
    const float* bkv  = (const float*)d_in[6];
    const float* btab = (const float*)d_in[7];
    const float* Wp   = (const float*)d_in[8];
    const float* bp   = (const float*)d_in[9];
    const int*   rel  = (const int*)d_in[10];
    float* out = (float*)d_out;

    static float* qh  = nullptr;
    static float* kvh = nullptr;
    static float* xb  = nullptr;
    if (!qh) {
        cudaGetSymbolAddress((void**)&qh,  d_qh);
        cudaGetSymbolAddress((void**)&kvh, d_kvh);
        cudaGetSymbolAddress((void**)&xb,  d_x);
    }

    const int M = BTOT * N1V;                       // 65536
    const float scale = 0.17677669529663687f;       // 1/sqrt(32)

    // 1) Q projection (scale folded): qh = scale * (q @ Wq^T + bq)
    gemm_nt<<<dim3(DIM / 128, M / 128), 256>>>(q, Wq, bq, qh, M, DIM, DIM, scale);
    // 2) KV projection: kvh = kv @ Wkv^T + bkv   (cols 0..255 = K, 256..511 = V)
    gemm_nt<<<dim3((2 * DIM) / 128, M / 128), 256>>>(kv, Wkv, bkv, kvh, M, 2 * DIM, DIM, 1.f);
    // 3) windowed attention with bias + mask + softmax
    attn_kernel<<<dim3(4, HEADS, BTOT), 256>>>(qh, kvh, mask, btab, rel, xb);
    // 4) output projection
    gemm_nt<<<dim3(DIM / 128, M / 128), 256>>>(xb, Wp, bp, out, M, DIM, DIM, 1.f);
}